// round 1
// baseline (speedup 1.0000x reference)
#include <cuda_runtime.h>
#include <math.h>

#define S      64
#define S2     4096
#define RF     15
#define RFP    225
#define INPUT  48
#define WR     14          // window half-width
#define WW     29          // window width
#define WN     841         // 29*29
#define ITERS  50

// thresholds for exc/inh (exact in f32)
#define TE (1.5f/4096.0f)
#define TI (1.0f/4096.0f)

// -------- device scratch (allowed: __device__ globals, bss-like) --------
__device__ float g_W2[S2 * S2];      // 64 MB  dense (exc - inh)
__device__ float g_l4w[S2 * WN];     // 13.8 MB windowed (lwe - mid)
__device__ float g_aff[S2];
__device__ float g_smid[S2];
__device__ float g_sexc[S2];
__device__ float g_sinh[S2];
__device__ float g_cur[2][S2];
__device__ float g_l4[2][S2];

// ---------------------------------------------------------------------------
// K_sums: per-row sums needed for normalization.
//   sexc = sum relu(lc - TE), sinh = sum relu(lc - TI)  (dense row)
//   smid = sum over circle(dist2<=156) of l4c            (29x29 window)
// ---------------------------------------------------------------------------
__global__ void K_sums(const float* __restrict__ lc, const float* __restrict__ l4c) {
    int row = blockIdx.x;
    int tid = threadIdx.x;
    int y = row >> 6, x = row & 63;

    float se = 0.f, si = 0.f, sm = 0.f;
    const float* lcrow = lc + (size_t)row * S2;
    for (int j = tid; j < S2; j += 256) {
        float v = lcrow[j];
        se += fmaxf(v - TE, 0.f);
        si += fmaxf(v - TI, 0.f);
    }
    const float* l4crow = l4c + (size_t)row * S2;
    for (int k = tid; k < WN; k += 256) {
        int dy = k / WW - WR;
        int dx = k % WW - WR;
        int yy = y + dy, xx = x + dx;
        int d2 = dy * dy + dx * dx;
        if (d2 <= 156 && (unsigned)yy < S && (unsigned)xx < S)
            sm += l4crow[yy * S + xx];
    }
    // block reduce 3 values
    __shared__ float red[3][8];
    for (int o = 16; o; o >>= 1) {
        se += __shfl_down_sync(0xffffffffu, se, o);
        si += __shfl_down_sync(0xffffffffu, si, o);
        sm += __shfl_down_sync(0xffffffffu, sm, o);
    }
    int w = tid >> 5, lane = tid & 31;
    if (lane == 0) { red[0][w] = se; red[1][w] = si; red[2][w] = sm; }
    __syncthreads();
    if (tid == 0) {
        float a = 0, b = 0, c = 0;
        for (int i = 0; i < 8; i++) { a += red[0][i]; b += red[1][i]; c += red[2][i]; }
        g_sexc[row] = a; g_sinh[row] = b; g_smid[row] = c;
    }
}

// ---------------------------------------------------------------------------
// K_build: materialize W2 (dense) and l4w (windowed).
// ---------------------------------------------------------------------------
__global__ void K_build(const float* __restrict__ lc, const float* __restrict__ l4c,
                        const float* __restrict__ lwe) {
    int row = blockIdx.x;
    int tid = threadIdx.x;
    int y = row >> 6, x = row & 63;

    float inv_e = 1.f / (g_sexc[row] + 1e-11f);
    float inv_i = 1.f / (g_sinh[row] + 1e-11f);
    float inv_m = 1.f / (g_smid[row] + 1e-11f);

    const float* lcrow = lc + (size_t)row * S2;
    float* w2row = g_W2 + (size_t)row * S2;
    for (int j = tid; j < S2; j += 256) {
        float v = lcrow[j];
        w2row[j] = fmaxf(v - TE, 0.f) * inv_e - fmaxf(v - TI, 0.f) * inv_i;
    }

    const float* l4crow = l4c + (size_t)row * S2;
    const float* lwerow = lwe + (size_t)row * S2;
    float* wrow = g_l4w + (size_t)row * WN;
    for (int k = tid; k < WN; k += 256) {
        int dy = k / WW - WR;
        int dx = k % WW - WR;
        int yy = y + dy, xx = x + dx;
        float wv = 0.f;
        if ((unsigned)yy < S && (unsigned)xx < S) {
            int j = yy * S + xx;
            int d2 = dy * dy + dx * dx;
            float mid = (d2 <= 156) ? l4crow[j] * inv_m : 0.f;
            wv = lwerow[j] - mid;
        }
        wrow[k] = wv;  // OOB entries are exactly 0 -> branchless gather later
    }
}

// ---------------------------------------------------------------------------
// K_aff: afferent drive per unit (one warp per unit).
// ---------------------------------------------------------------------------
__global__ void K_aff(const float* __restrict__ img, const int* __restrict__ grids,
                      const float* __restrict__ affw) {
    int unit = blockIdx.x * 8 + (threadIdx.x >> 5);
    int lane = threadIdx.x & 31;
    float a = 0.f;
    const int* g = grids + (size_t)unit * RFP * 2;
    const float* w = affw + (size_t)unit * RFP;
    for (int p = lane; p < RFP; p += 32) {
        int r = g[p * 2 + 0];
        int c = g[p * 2 + 1];
        a += img[r * INPUT + c] * w[p];
    }
    for (int o = 16; o; o >>= 1) a += __shfl_down_sync(0xffffffffu, a, o);
    if (lane == 0) g_aff[unit] = a;
}

// ---------------------------------------------------------------------------
// K_init: zero the state buffers.
// ---------------------------------------------------------------------------
__global__ void K_init() {
    int i = blockIdx.x * blockDim.x + threadIdx.x;
    if (i < S2) { g_cur[0][i] = 0.f; g_l4[0][i] = 0.f; }
}

// ---------------------------------------------------------------------------
// K_iter: one settling step. 512 blocks x 256 threads; one warp per row.
// ---------------------------------------------------------------------------
__global__ void __launch_bounds__(256) K_iter(int src, int dst,
                                              const float* __restrict__ thr,
                                              const float* __restrict__ l4thr,
                                              float* __restrict__ out, int last) {
    __shared__ float scur[S2];
    __shared__ float sl4[S2];
    int tid = threadIdx.x;

    // stage both state vectors (1024 float4 each)
    {
        const float4* c4 = (const float4*)g_cur[src];
        const float4* l4p = (const float4*)g_l4[src];
        float4* sc = (float4*)scur;
        float4* sl = (float4*)sl4;
        for (int i = tid; i < S2 / 4; i += 256) { sc[i] = c4[i]; sl[i] = l4p[i]; }
    }
    __syncthreads();

    int warp = tid >> 5, lane = tid & 31;
    int row = blockIdx.x * 8 + warp;
    int y = row >> 6, x = row & 63;

    // dense part: W2 @ cur
    float accd = 0.f;
    const float4* wrow = (const float4*)(g_W2 + (size_t)row * S2);
    const float4* xv = (const float4*)scur;
#pragma unroll 8
    for (int t = 0; t < 32; t++) {
        float4 a = wrow[lane + t * 32];
        float4 b = xv[lane + t * 32];
        accd += a.x * b.x + a.y * b.y + a.z * b.z + a.w * b.w;
    }

    // windowed part: l4w @ l4 (branchless: OOB weights are 0, indices clamped)
    float accw = 0.f;
    const float* lw = g_l4w + (size_t)row * WN;
#pragma unroll 4
    for (int k = lane; k < WN; k += 32) {
        int dy = k / WW - WR;
        int dx = k % WW - WR;
        int yy = min(max(y + dy, 0), S - 1);
        int xx = min(max(x + dx, 0), S - 1);
        accw += lw[k] * sl4[yy * S + xx];
    }

    for (int o = 16; o; o >>= 1) {
        accd += __shfl_down_sync(0xffffffffu, accd, o);
        accw += __shfl_down_sync(0xffffffffu, accw, o);
    }

    if (lane == 0) {
        // b = 0.5/(0.5+1e-11) rounds to exactly 1.0f in f32 weak typing
        float l4_aff = 0.5f * (g_aff[row] + scur[row]);
        float l4n = tanhf(fmaxf(l4_aff + accw - l4thr[row], 0.f) * 2.0f);
        float curn = tanhf(fmaxf(l4n + accd - thr[row], 0.f));
        g_l4[dst][row] = l4n;
        g_cur[dst][row] = curn;
        if (last) out[row] = curn;
    }
}

// ---------------------------------------------------------------------------
extern "C" void kernel_launch(void* const* d_in, const int* in_sizes, int n_in,
                              void* d_out, int out_size) {
    const float* img   = (const float*)d_in[0];
    const int*   grids = (const int*)d_in[1];
    const float* affw  = (const float*)d_in[2];
    const float* lc    = (const float*)d_in[3];
    const float* l4c   = (const float*)d_in[4];
    const float* lwe   = (const float*)d_in[5];
    // d_in[6] = masks (derivable: 1 - circle indicator; unused)
    const float* thr   = (const float*)d_in[7];
    const float* l4thr = (const float*)d_in[8];
    float* out = (float*)d_out;

    K_sums<<<S2, 256>>>(lc, l4c);
    K_build<<<S2, 256>>>(lc, l4c, lwe);
    K_aff<<<S2 / 8, 256>>>(img, grids, affw);
    K_init<<<(S2 + 255) / 256, 256>>>();

    for (int i = 0; i < ITERS; i++) {
        K_iter<<<S2 / 8, 256>>>(i & 1, (i + 1) & 1, thr, l4thr, out, i == ITERS - 1);
    }
}